// round 13
// baseline (speedup 1.0000x reference)
#include <cuda_runtime.h>
#include <cuda_fp16.h>
#include <cstdint>

#define N_NODES  50000
#define N_EDGES  640000
#define D        128
#define N_GRAPHS 64
#define CAP      64                  // per-node edge bucket capacity

#define GEMM_BLOCKS   391            // ceil(50000/128)
#define FILL_BLOCKS   625            // 640000 / (256*4)
#define DINV_BLOCKS   196            // ceil(50000/256)
#define CLEAN_BLOCKS  200            // 64 out-gemm + 136 cleanup
#define GATHER_BLOCKS 6250           // 50000 / 8 warps (1 warp per node)

// ---------------- scratch (device globals; zero-initialized at load) --------
// INVARIANT: g_fill and g_y are zero on entry to kernel_launch and re-zeroed
// by the tail kernel, so every graph replay sees clean state.
__device__ __half g_h16[N_NODES * D];           // gemm1 output (fp16)
__device__ __half g_z16[N_NODES * D];           // layer-1 activation (fp16)
__device__ int    g_fill[N_NODES];              // bucket cursors == degrees
__device__ float  g_dinv[N_NODES];
// bucket CSR. fill writes raw src ids each call; gather1 rewrites each live
// entry in-place as: low 16 = src id (N_NODES < 65536), high 16 = fp16 norm,
// which gather2 consumes. Slots >= deg are never read; src ids < 65536 so
// "& 0xFFFF" is identity on both raw and packed forms.
__device__ __align__(16) unsigned g_sbuf[N_NODES * CAP];
__device__ float  g_y[N_GRAPHS * D];            // pooled sums (atomic accum)

// ---------------- helpers ----------------------------------------------------
__device__ __forceinline__ unsigned h2u(__half2 h) {
    union { __half2 h; unsigned u; } c; c.h = h; return c.u;
}
__device__ __forceinline__ __half2 u2h(unsigned u) {
    union { unsigned u; __half2 h; } c; c.u = u; return c.h;
}

// ---------------- GEMM1: h16[M,128] = fp16( X @ W1 ), tensor cores ----------
__global__ void __launch_bounds__(256) gemm_mma_kernel(
        const float* __restrict__ X, const float* __restrict__ W,
        __half* __restrict__ OUT16) {
    __shared__ __half As[128][72];
    __shared__ __half Bs[128][72];

    const int tid  = threadIdx.x;
    const int warp = tid >> 5;
    const int lane = tid & 31;
    const int g    = lane >> 2;
    const int t    = lane & 3;
    const int row0 = blockIdx.x * 128;
    const int wrow = warp * 16;

    float c[16][4];
#pragma unroll
    for (int j = 0; j < 16; ++j)
#pragma unroll
        for (int q = 0; q < 4; ++q) c[j][q] = 0.f;

    for (int stage = 0; stage < 2; ++stage) {
        const int k0 = stage * 64;
#pragma unroll
        for (int it = 0; it < 8; ++it) {
            int f4  = it * 256 + tid;
            int row = f4 >> 4;
            int c4  = f4 & 15;
            float4 v = make_float4(0.f, 0.f, 0.f, 0.f);
            if (row0 + row < N_NODES)
                v = *(const float4*)&X[(size_t)(row0 + row) * D + k0 + c4 * 4];
            __half2 h0 = __floats2half2_rn(v.x, v.y);
            __half2 h1 = __floats2half2_rn(v.z, v.w);
            uint2 pk; pk.x = h2u(h0); pk.y = h2u(h1);
            *(uint2*)&As[row][c4 * 4] = pk;
        }
#pragma unroll
        for (int it = 0; it < 16; ++it) {
            int p  = it * 256 + tid;
            int n  = p & 127;
            int kp = p >> 7;
            float w0 = W[(size_t)(k0 + 2 * kp) * D + n];
            float w1 = W[(size_t)(k0 + 2 * kp + 1) * D + n];
            __half2 h = __floats2half2_rn(w0, w1);
            *(unsigned*)&Bs[n][2 * kp] = h2u(h);
        }
        __syncthreads();

#pragma unroll
        for (int ks = 0; ks < 4; ++ks) {
            unsigned ra0 = *(const unsigned*)&As[wrow + g][ks * 16 + t * 2];
            unsigned ra1 = *(const unsigned*)&As[wrow + g + 8][ks * 16 + t * 2];
            unsigned ra2 = *(const unsigned*)&As[wrow + g][ks * 16 + t * 2 + 8];
            unsigned ra3 = *(const unsigned*)&As[wrow + g + 8][ks * 16 + t * 2 + 8];
#pragma unroll
            for (int j = 0; j < 16; ++j) {
                unsigned rb0 = *(const unsigned*)&Bs[j * 8 + g][ks * 16 + t * 2];
                unsigned rb1 = *(const unsigned*)&Bs[j * 8 + g][ks * 16 + t * 2 + 8];
                asm volatile(
                    "mma.sync.aligned.m16n8k16.row.col.f32.f16.f16.f32 "
                    "{%0,%1,%2,%3}, {%4,%5,%6,%7}, {%8,%9}, {%0,%1,%2,%3};"
                    : "+f"(c[j][0]), "+f"(c[j][1]), "+f"(c[j][2]), "+f"(c[j][3])
                    : "r"(ra0), "r"(ra1), "r"(ra2), "r"(ra3), "r"(rb0), "r"(rb1));
            }
        }
        __syncthreads();
    }

    int row_a = row0 + wrow + g;
    int row_b = row_a + 8;
#pragma unroll
    for (int j = 0; j < 16; ++j) {
        if (row_a < N_NODES) {
            __half2 p = __floats2half2_rn(c[j][0], c[j][1]);
            *(unsigned*)&OUT16[(size_t)row_a * D + j * 8 + t * 2] = h2u(p);
        }
        if (row_b < N_NODES) {
            __half2 p = __floats2half2_rn(c[j][2], c[j][3]);
            *(unsigned*)&OUT16[(size_t)row_b * D + j * 8 + t * 2] = h2u(p);
        }
    }
}

// ---------------- bucket CSR fill: 4 edges per thread ------------------------
__global__ void __launch_bounds__(256) fill_kernel(const int* __restrict__ ei) {
    int i = (blockIdx.x * 256 + threadIdx.x) * 4;   // exact 640000
    int4 s4 = *(const int4*)&ei[i];
    int4 d4 = *(const int4*)&ei[N_EDGES + i];
    int p0 = atomicAdd(&g_fill[d4.x], 1);
    int p1 = atomicAdd(&g_fill[d4.y], 1);
    int p2 = atomicAdd(&g_fill[d4.z], 1);
    int p3 = atomicAdd(&g_fill[d4.w], 1);
    if (p0 < CAP) g_sbuf[d4.x * CAP + p0] = (unsigned)s4.x;
    if (p1 < CAP) g_sbuf[d4.y * CAP + p1] = (unsigned)s4.y;
    if (p2 < CAP) g_sbuf[d4.z * CAP + p2] = (unsigned)s4.z;
    if (p3 < CAP) g_sbuf[d4.w * CAP + p3] = (unsigned)s4.w;
}

__global__ void dinv_kernel() {
    int i = blockIdx.x * 256 + threadIdx.x;
    if (i < N_NODES) g_dinv[i] = rsqrtf((float)(g_fill[i] + 1));
}

// ---------------- gather cores ------------------------------------------------
__device__ __forceinline__ void acc_row_self(const __half* __restrict__ H,
                                             int node, int lane, float nm,
                                             __half2& a0, __half2& a1) {
    uint2 u = ((const uint2*)(H + (size_t)node * D))[lane];
    __half2 nm2 = __float2half2_rn(nm);
    a0 = __hfma2(u2h(u.x), nm2, a0);
    a1 = __hfma2(u2h(u.y), nm2, a1);
}

// gather1 edge: compute nm from dinv (uniform load), accumulate, return packed.
__device__ __forceinline__ unsigned pack_acc_edge(
        const __half* __restrict__ H, unsigned raw, float dd, int lane,
        __half2& a0, __half2& a1) {
    unsigned s = raw & 0xFFFFu;
    __half nm = __float2half(g_dinv[s] * dd);
    __half2 nm2 = __half2half2(nm);
    uint2 u = ((const uint2*)(H + (size_t)s * D))[lane];
    a0 = __hfma2(u2h(u.x), nm2, a0);
    a1 = __hfma2(u2h(u.y), nm2, a1);
    return s | ((unsigned)__half_as_ushort(nm) << 16);
}

// gather2 edge: consume packed entry.
__device__ __forceinline__ void acc_edge_pk(const __half* __restrict__ H,
                                            unsigned pk, int lane,
                                            __half2& a0, __half2& a1) {
    int s = (int)(pk & 0xFFFFu);
    __half2 nm2 = u2h(__byte_perm(pk, pk, 0x3232));   // (nm, nm)
    uint2 u = ((const uint2*)(H + (size_t)s * D))[lane];
    a0 = __hfma2(u2h(u.x), nm2, a0);
    a1 = __hfma2(u2h(u.y), nm2, a1);
}

// layer-1: z16 = fp16( relu( Ahat*h + b1 ) ); one warp per node.
// Also rewrites bucket entries packed (src | fp16-nm<<16) for gather2.
__global__ void __launch_bounds__(256) gather1_kernel(
        const float* __restrict__ bias) {
    int node = (blockIdx.x * blockDim.x + threadIdx.x) >> 5;   // exact 50000
    const int lane = threadIdx.x & 31;

    int deg = g_fill[node];
    int degc = deg < CAP ? deg : CAP;
    float dd = g_dinv[node];
    __half2 a0 = __float2half2_rn(0.f), a1 = __float2half2_rn(0.f);
    acc_row_self(g_h16, node, lane, dd * dd, a0, a1);

    uint4* sb = (uint4*)(g_sbuf + node * CAP);
    int e = 0;
    for (; e + 8 <= degc; e += 8) {
        uint4 sa = sb[e >> 2];
        uint4 sc = sb[(e >> 2) + 1];
        uint4 pa, pc;
        pa.x = pack_acc_edge(g_h16, sa.x, dd, lane, a0, a1);
        pa.y = pack_acc_edge(g_h16, sa.y, dd, lane, a0, a1);
        pa.z = pack_acc_edge(g_h16, sa.z, dd, lane, a0, a1);
        pa.w = pack_acc_edge(g_h16, sa.w, dd, lane, a0, a1);
        pc.x = pack_acc_edge(g_h16, sc.x, dd, lane, a0, a1);
        pc.y = pack_acc_edge(g_h16, sc.y, dd, lane, a0, a1);
        pc.z = pack_acc_edge(g_h16, sc.z, dd, lane, a0, a1);
        pc.w = pack_acc_edge(g_h16, sc.w, dd, lane, a0, a1);
        if (lane == 0) { sb[e >> 2] = pa; sb[(e >> 2) + 1] = pc; }
    }
    if (e + 4 <= degc) {
        uint4 sa = sb[e >> 2];
        uint4 pa;
        pa.x = pack_acc_edge(g_h16, sa.x, dd, lane, a0, a1);
        pa.y = pack_acc_edge(g_h16, sa.y, dd, lane, a0, a1);
        pa.z = pack_acc_edge(g_h16, sa.z, dd, lane, a0, a1);
        pa.w = pack_acc_edge(g_h16, sa.w, dd, lane, a0, a1);
        if (lane == 0) sb[e >> 2] = pa;
        e += 4;
    }
    for (; e < degc; ++e) {
        unsigned p = pack_acc_edge(g_h16, g_sbuf[node * CAP + e], dd, lane, a0, a1);
        if (lane == 0) g_sbuf[node * CAP + e] = p;
    }

    float2 f0 = __half22float2(a0);
    float2 f1 = __half22float2(a1);
    float4 b = *(const float4*)&bias[lane * 4];
    float rx = fmaxf(f0.x + b.x, 0.f);
    float ry = fmaxf(f0.y + b.y, 0.f);
    float rz = fmaxf(f1.x + b.z, 0.f);
    float rw = fmaxf(f1.y + b.w, 0.f);
    __half2 p0 = __floats2half2_rn(rx, ry);
    __half2 p1 = __floats2half2_rn(rz, rw);
    uint2 pk; pk.x = h2u(p0); pk.y = h2u(p1);
    ((uint2*)(g_z16 + (size_t)node * D))[lane] = pk;
}

// layer-2 + fused pool: g_y[batch[node]] += Ahat*z  (block = 8 nodes)
__global__ void __launch_bounds__(256) gather2_kernel(
        const int* __restrict__ batch) {
    __shared__ float part[8][128];
    __shared__ int   sgr[8];

    int node = (blockIdx.x * blockDim.x + threadIdx.x) >> 5;   // exact 50000
    const int warp = threadIdx.x >> 5;
    const int lane = threadIdx.x & 31;

    int deg = g_fill[node];
    int degc = deg < CAP ? deg : CAP;
    float dd = g_dinv[node];
    __half2 a0 = __float2half2_rn(0.f), a1 = __float2half2_rn(0.f);
    acc_row_self(g_z16, node, lane, dd * dd, a0, a1);

    const uint4* sb = (const uint4*)(g_sbuf + node * CAP);
    int e = 0;
    for (; e + 8 <= degc; e += 8) {
        uint4 sa = sb[e >> 2];
        uint4 sc = sb[(e >> 2) + 1];
        acc_edge_pk(g_z16, sa.x, lane, a0, a1);
        acc_edge_pk(g_z16, sa.y, lane, a0, a1);
        acc_edge_pk(g_z16, sa.z, lane, a0, a1);
        acc_edge_pk(g_z16, sa.w, lane, a0, a1);
        acc_edge_pk(g_z16, sc.x, lane, a0, a1);
        acc_edge_pk(g_z16, sc.y, lane, a0, a1);
        acc_edge_pk(g_z16, sc.z, lane, a0, a1);
        acc_edge_pk(g_z16, sc.w, lane, a0, a1);
    }
    if (e + 4 <= degc) {
        uint4 sa = sb[e >> 2];
        acc_edge_pk(g_z16, sa.x, lane, a0, a1);
        acc_edge_pk(g_z16, sa.y, lane, a0, a1);
        acc_edge_pk(g_z16, sa.z, lane, a0, a1);
        acc_edge_pk(g_z16, sa.w, lane, a0, a1);
        e += 4;
    }
    for (; e < degc; ++e) {
        acc_edge_pk(g_z16, g_sbuf[node * CAP + e], lane, a0, a1);
    }

    float2 f0 = __half22float2(a0);
    float2 f1 = __half22float2(a1);
    *(float4*)&part[warp][lane * 4] = make_float4(f0.x, f0.y, f1.x, f1.y);
    if (lane == 0) sgr[warp] = batch[node];
    __syncthreads();

    if (threadIdx.x < 128) {
        int d = threadIdx.x;
        float acc = part[0][d];
        int gc = sgr[0];
#pragma unroll
        for (int w = 1; w < 8; ++w) {
            int gw = sgr[w];
            if (gw != gc) {
                atomicAdd(&g_y[gc * D + d], acc);
                acc = 0.f; gc = gw;
            }
            acc += part[w][d];
        }
        atomicAdd(&g_y[gc * D + d], acc);
    }
}

// out[g] = (g_y[g]/cnt_g) @ W2 + b2 ; cnt via binary search on sorted batch;
// then restore zeroed-scratch invariant.
__global__ void out_clean_kernel(const int* __restrict__ batch,
                                 const float* __restrict__ W2,
                                 const float* __restrict__ b2,
                                 float* __restrict__ out) {
    int b = blockIdx.x;
    if (b < N_GRAPHS) {
        __shared__ float ys[D];
        int g = b, d = threadIdx.x;
        int lo = 0, hi = N_NODES;
        while (lo < hi) { int m = (lo + hi) >> 1; if (batch[m] < g) lo = m + 1; else hi = m; }
        int start = lo;
        lo = 0; hi = N_NODES;
        while (lo < hi) { int m = (lo + hi) >> 1; if (batch[m] < g + 1) lo = m + 1; else hi = m; }
        float cnt = fmaxf((float)(lo - start), 1.f);

        ys[d] = g_y[g * D + d] / cnt;
        g_y[g * D + d] = 0.f;            // restore invariant
        __syncthreads();
        float acc = b2[d];
#pragma unroll 8
        for (int k = 0; k < D; ++k) acc += ys[k] * W2[k * D + d];
        out[g * D + d] = acc;
    } else {
        const int nthr = (CLEAN_BLOCKS - N_GRAPHS) * 128;
        int i = (b - N_GRAPHS) * 128 + threadIdx.x;
        for (int j = i; j < N_NODES; j += nthr) g_fill[j] = 0;
    }
}

// ---------------- launch -----------------------------------------------------

extern "C" void kernel_launch(void* const* d_in, const int* in_sizes, int n_in,
                              void* d_out, int out_size) {
    const float* x     = (const float*)d_in[0];
    const int*   ei    = (const int*)d_in[1];    // int32 (JAX x64 disabled)
    const int*   batch = (const int*)d_in[2];
    const float* W1    = (const float*)d_in[3];
    const float* b1    = (const float*)d_in[4];
    const float* W2    = (const float*)d_in[5];
    const float* b2    = (const float*)d_in[6];
    float*       out   = (float*)d_out;

    __half* h16; cudaGetSymbolAddress((void**)&h16, g_h16);

    static cudaStream_t s_side = nullptr;
    static cudaEvent_t  e_fork = nullptr, e_join = nullptr;
    if (s_side == nullptr) {
        cudaStreamCreateWithFlags(&s_side, cudaStreamNonBlocking);
        cudaEventCreateWithFlags(&e_fork, cudaEventDisableTiming);
        cudaEventCreateWithFlags(&e_join, cudaEventDisableTiming);
    }

    // fork: main = GEMM1 (tensor cores) ; side = bucket fill -> dinv
    cudaEventRecord(e_fork, 0);
    cudaStreamWaitEvent(s_side, e_fork, 0);

    gemm_mma_kernel<<<GEMM_BLOCKS, 256>>>(x, W1, h16);

    fill_kernel<<<FILL_BLOCKS, 256, 0, s_side>>>(ei);
    dinv_kernel<<<DINV_BLOCKS, 256, 0, s_side>>>();

    cudaEventRecord(e_join, s_side);
    cudaStreamWaitEvent(0, e_join, 0);

    // join: gather1 (computes norms, packs bucket) -> gather2 (packed fast path)
    gather1_kernel<<<GATHER_BLOCKS, 256>>>(b1);
    gather2_kernel<<<GATHER_BLOCKS, 256>>>(batch);
    out_clean_kernel<<<CLEAN_BLOCKS, D>>>(batch, W2, b2, out);
}

// round 14
// speedup vs baseline: 1.0641x; 1.0641x over previous
#include <cuda_runtime.h>
#include <cuda_fp16.h>
#include <cstdint>

#define N_NODES  50000
#define N_EDGES  640000
#define D        128
#define N_GRAPHS 64
#define CAP      64                  // per-node edge bucket capacity

#define GEMM_BLOCKS   391            // ceil(50000/128)
#define FILL_BLOCKS   2500           // 640000/256 (1 edge per thread)
#define DINV_BLOCKS   196            // ceil(50000/256)
#define PACK_BLOCKS   3125           // 50000*16 / 256
#define CLEAN_BLOCKS  200            // 64 out-gemm + 136 cleanup
#define GATHER_BLOCKS 6250           // 50000 / 8 warps (1 warp per node)

// ---------------- scratch (device globals; zero-initialized at load) --------
// INVARIANT: g_fill and g_y are zero on entry to kernel_launch and re-zeroed
// by the tail kernel, so every graph replay sees clean state.
__device__ __half g_h16[N_NODES * D];           // gemm1 output (fp16)
__device__ __half g_z16[N_NODES * D];           // layer-1 activation (fp16)
__device__ int    g_fill[N_NODES];              // bucket cursors == degrees
__device__ float  g_dinv[N_NODES];
// raw bucket CSR: src ids (always raw; slots >= deg never read)
__device__ __align__(16) unsigned g_sbuf[N_NODES * CAP];
// packed bucket CSR for gather2: low 16 = src id, high 16 = fp16 norm
__device__ __align__(16) unsigned g_pbuf[N_NODES * CAP];
__device__ float  g_y[N_GRAPHS * D];            // pooled sums (atomic accum)

// ---------------- helpers ----------------------------------------------------
__device__ __forceinline__ unsigned h2u(__half2 h) {
    union { __half2 h; unsigned u; } c; c.h = h; return c.u;
}
__device__ __forceinline__ __half2 u2h(unsigned u) {
    union { unsigned u; __half2 h; } c; c.u = u; return c.h;
}

// ---------------- GEMM1: h16[M,128] = fp16( X @ W1 ), tensor cores ----------
__global__ void __launch_bounds__(256) gemm_mma_kernel(
        const float* __restrict__ X, const float* __restrict__ W,
        __half* __restrict__ OUT16) {
    __shared__ __half As[128][72];
    __shared__ __half Bs[128][72];

    const int tid  = threadIdx.x;
    const int warp = tid >> 5;
    const int lane = tid & 31;
    const int g    = lane >> 2;
    const int t    = lane & 3;
    const int row0 = blockIdx.x * 128;
    const int wrow = warp * 16;

    float c[16][4];
#pragma unroll
    for (int j = 0; j < 16; ++j)
#pragma unroll
        for (int q = 0; q < 4; ++q) c[j][q] = 0.f;

    for (int stage = 0; stage < 2; ++stage) {
        const int k0 = stage * 64;
#pragma unroll
        for (int it = 0; it < 8; ++it) {
            int f4  = it * 256 + tid;
            int row = f4 >> 4;
            int c4  = f4 & 15;
            float4 v = make_float4(0.f, 0.f, 0.f, 0.f);
            if (row0 + row < N_NODES)
                v = *(const float4*)&X[(size_t)(row0 + row) * D + k0 + c4 * 4];
            __half2 h0 = __floats2half2_rn(v.x, v.y);
            __half2 h1 = __floats2half2_rn(v.z, v.w);
            uint2 pk; pk.x = h2u(h0); pk.y = h2u(h1);
            *(uint2*)&As[row][c4 * 4] = pk;
        }
#pragma unroll
        for (int it = 0; it < 16; ++it) {
            int p  = it * 256 + tid;
            int n  = p & 127;
            int kp = p >> 7;
            float w0 = W[(size_t)(k0 + 2 * kp) * D + n];
            float w1 = W[(size_t)(k0 + 2 * kp + 1) * D + n];
            __half2 h = __floats2half2_rn(w0, w1);
            *(unsigned*)&Bs[n][2 * kp] = h2u(h);
        }
        __syncthreads();

#pragma unroll
        for (int ks = 0; ks < 4; ++ks) {
            unsigned ra0 = *(const unsigned*)&As[wrow + g][ks * 16 + t * 2];
            unsigned ra1 = *(const unsigned*)&As[wrow + g + 8][ks * 16 + t * 2];
            unsigned ra2 = *(const unsigned*)&As[wrow + g][ks * 16 + t * 2 + 8];
            unsigned ra3 = *(const unsigned*)&As[wrow + g + 8][ks * 16 + t * 2 + 8];
#pragma unroll
            for (int j = 0; j < 16; ++j) {
                unsigned rb0 = *(const unsigned*)&Bs[j * 8 + g][ks * 16 + t * 2];
                unsigned rb1 = *(const unsigned*)&Bs[j * 8 + g][ks * 16 + t * 2 + 8];
                asm volatile(
                    "mma.sync.aligned.m16n8k16.row.col.f32.f16.f16.f32 "
                    "{%0,%1,%2,%3}, {%4,%5,%6,%7}, {%8,%9}, {%0,%1,%2,%3};"
                    : "+f"(c[j][0]), "+f"(c[j][1]), "+f"(c[j][2]), "+f"(c[j][3])
                    : "r"(ra0), "r"(ra1), "r"(ra2), "r"(ra3), "r"(rb0), "r"(rb1));
            }
        }
        __syncthreads();
    }

    int row_a = row0 + wrow + g;
    int row_b = row_a + 8;
#pragma unroll
    for (int j = 0; j < 16; ++j) {
        if (row_a < N_NODES) {
            __half2 p = __floats2half2_rn(c[j][0], c[j][1]);
            *(unsigned*)&OUT16[(size_t)row_a * D + j * 8 + t * 2] = h2u(p);
        }
        if (row_b < N_NODES) {
            __half2 p = __floats2half2_rn(c[j][2], c[j][3]);
            *(unsigned*)&OUT16[(size_t)row_b * D + j * 8 + t * 2] = h2u(p);
        }
    }
}

// ---------------- bucket CSR fill (1 edge per thread; r11-proven) ------------
__global__ void fill_kernel(const int* __restrict__ ei) {
    int i = blockIdx.x * 256 + threadIdx.x;        // exact 640000
    int src = ei[i];
    int dst = ei[N_EDGES + i];
    int pos = atomicAdd(&g_fill[dst], 1);
    if (pos < CAP) g_sbuf[dst * CAP + pos] = (unsigned)src;
}

__global__ void dinv_kernel() {
    int i = blockIdx.x * 256 + threadIdx.x;
    if (i < N_NODES) g_dinv[i] = rsqrtf((float)(g_fill[i] + 1));
}

// Pack into g_pbuf (thread-per-4-slots). Runs concurrently with gather1
// (gather1 only READS g_sbuf/g_dinv; no conflict).
__global__ void __launch_bounds__(256) pack_kernel() {
    int t = blockIdx.x * 256 + threadIdx.x;        // exact 800000
    int node = t >> 4;
    int base = (t & 15) * 4;
    int deg = g_fill[node];
    int degc = deg < CAP ? deg : CAP;
    if (base >= degc) return;
    float dd = g_dinv[node];
    uint4 v = *(const uint4*)&g_sbuf[node * CAP + base];
    int n = degc - base;
    uint4 p;
    p.x = v.x | ((unsigned)__half_as_ushort(__float2half(g_dinv[v.x] * dd)) << 16);
    p.y = (n > 1) ? (v.y | ((unsigned)__half_as_ushort(__float2half(g_dinv[v.y] * dd)) << 16)) : 0u;
    p.z = (n > 2) ? (v.z | ((unsigned)__half_as_ushort(__float2half(g_dinv[v.z] * dd)) << 16)) : 0u;
    p.w = (n > 3) ? (v.w | ((unsigned)__half_as_ushort(__float2half(g_dinv[v.w] * dd)) << 16)) : 0u;
    *(uint4*)&g_pbuf[node * CAP + base] = p;
}

// ---------------- gather cores ------------------------------------------------
__device__ __forceinline__ void acc_row_self(const __half* __restrict__ H,
                                             int node, int lane, float nm,
                                             __half2& a0, __half2& a1) {
    uint2 u = ((const uint2*)(H + (size_t)node * D))[lane];
    __half2 nm2 = __float2half2_rn(nm);
    a0 = __hfma2(u2h(u.x), nm2, a0);
    a1 = __hfma2(u2h(u.y), nm2, a1);
}

// gather1 edge (raw id; nm from uniform dinv load) — r10-proven hot loop.
__device__ __forceinline__ void acc_row_hf(const __half* __restrict__ H,
                                           unsigned srcnode, int lane, float nm,
                                           __half2& a0, __half2& a1) {
    uint2 u = ((const uint2*)(H + (size_t)srcnode * D))[lane];
    __half2 nm2 = __float2half2_rn(nm);
    a0 = __hfma2(u2h(u.x), nm2, a0);
    a1 = __hfma2(u2h(u.y), nm2, a1);
}

// gather2 edge: consume packed entry.
__device__ __forceinline__ void acc_edge_pk(const __half* __restrict__ H,
                                            unsigned pk, int lane,
                                            __half2& a0, __half2& a1) {
    int s = (int)(pk & 0xFFFFu);
    __half2 nm2 = u2h(__byte_perm(pk, pk, 0x3232));   // (nm, nm)
    uint2 u = ((const uint2*)(H + (size_t)s * D))[lane];
    a0 = __hfma2(u2h(u.x), nm2, a0);
    a1 = __hfma2(u2h(u.y), nm2, a1);
}

// layer-1: z16 = fp16( relu( Ahat*h + b1 ) );  one warp per node (raw bucket)
__global__ void __launch_bounds__(256) gather1_kernel(
        const float* __restrict__ bias) {
    int node = (blockIdx.x * blockDim.x + threadIdx.x) >> 5;   // exact 50000
    const int lane = threadIdx.x & 31;

    float dd = g_dinv[node];
    __half2 a0 = __float2half2_rn(0.f), a1 = __float2half2_rn(0.f);
    acc_row_self(g_h16, node, lane, dd * dd, a0, a1);

    int deg = g_fill[node];
    int degc = deg < CAP ? deg : CAP;
    const uint4* sb = (const uint4*)(g_sbuf + node * CAP);
    int e = 0;
    for (; e + 8 <= degc; e += 8) {
        uint4 sa = sb[e >> 2];
        uint4 sc = sb[(e >> 2) + 1];
        float n0 = g_dinv[sa.x] * dd;
        float n1 = g_dinv[sa.y] * dd;
        float n2 = g_dinv[sa.z] * dd;
        float n3 = g_dinv[sa.w] * dd;
        float n4 = g_dinv[sc.x] * dd;
        float n5 = g_dinv[sc.y] * dd;
        float n6 = g_dinv[sc.z] * dd;
        float n7 = g_dinv[sc.w] * dd;
        acc_row_hf(g_h16, sa.x, lane, n0, a0, a1);
        acc_row_hf(g_h16, sa.y, lane, n1, a0, a1);
        acc_row_hf(g_h16, sa.z, lane, n2, a0, a1);
        acc_row_hf(g_h16, sa.w, lane, n3, a0, a1);
        acc_row_hf(g_h16, sc.x, lane, n4, a0, a1);
        acc_row_hf(g_h16, sc.y, lane, n5, a0, a1);
        acc_row_hf(g_h16, sc.z, lane, n6, a0, a1);
        acc_row_hf(g_h16, sc.w, lane, n7, a0, a1);
    }
    if (e + 4 <= degc) {
        uint4 sa = sb[e >> 2];
        float n0 = g_dinv[sa.x] * dd;
        float n1 = g_dinv[sa.y] * dd;
        float n2 = g_dinv[sa.z] * dd;
        float n3 = g_dinv[sa.w] * dd;
        acc_row_hf(g_h16, sa.x, lane, n0, a0, a1);
        acc_row_hf(g_h16, sa.y, lane, n1, a0, a1);
        acc_row_hf(g_h16, sa.z, lane, n2, a0, a1);
        acc_row_hf(g_h16, sa.w, lane, n3, a0, a1);
        e += 4;
    }
    for (; e < degc; ++e) {
        unsigned s = g_sbuf[node * CAP + e];
        acc_row_hf(g_h16, s, lane, g_dinv[s] * dd, a0, a1);
    }

    float2 f0 = __half22float2(a0);
    float2 f1 = __half22float2(a1);
    float4 b = *(const float4*)&bias[lane * 4];
    float rx = fmaxf(f0.x + b.x, 0.f);
    float ry = fmaxf(f0.y + b.y, 0.f);
    float rz = fmaxf(f1.x + b.z, 0.f);
    float rw = fmaxf(f1.y + b.w, 0.f);
    __half2 p0 = __floats2half2_rn(rx, ry);
    __half2 p1 = __floats2half2_rn(rz, rw);
    uint2 pk; pk.x = h2u(p0); pk.y = h2u(p1);
    ((uint2*)(g_z16 + (size_t)node * D))[lane] = pk;
}

// layer-2 + fused pool: g_y[batch[node]] += Ahat*z  (block = 8 nodes; packed)
__global__ void __launch_bounds__(256) gather2_kernel(
        const int* __restrict__ batch) {
    __shared__ float part[8][128];
    __shared__ int   sgr[8];

    int node = (blockIdx.x * blockDim.x + threadIdx.x) >> 5;   // exact 50000
    const int warp = threadIdx.x >> 5;
    const int lane = threadIdx.x & 31;

    float dd = g_dinv[node];
    __half2 a0 = __float2half2_rn(0.f), a1 = __float2half2_rn(0.f);
    acc_row_self(g_z16, node, lane, dd * dd, a0, a1);

    int deg = g_fill[node];
    int degc = deg < CAP ? deg : CAP;
    const uint4* sb = (const uint4*)(g_pbuf + node * CAP);
    int e = 0;
    for (; e + 8 <= degc; e += 8) {
        uint4 sa = sb[e >> 2];
        uint4 sc = sb[(e >> 2) + 1];
        acc_edge_pk(g_z16, sa.x, lane, a0, a1);
        acc_edge_pk(g_z16, sa.y, lane, a0, a1);
        acc_edge_pk(g_z16, sa.z, lane, a0, a1);
        acc_edge_pk(g_z16, sa.w, lane, a0, a1);
        acc_edge_pk(g_z16, sc.x, lane, a0, a1);
        acc_edge_pk(g_z16, sc.y, lane, a0, a1);
        acc_edge_pk(g_z16, sc.z, lane, a0, a1);
        acc_edge_pk(g_z16, sc.w, lane, a0, a1);
    }
    if (e + 4 <= degc) {
        uint4 sa = sb[e >> 2];
        acc_edge_pk(g_z16, sa.x, lane, a0, a1);
        acc_edge_pk(g_z16, sa.y, lane, a0, a1);
        acc_edge_pk(g_z16, sa.z, lane, a0, a1);
        acc_edge_pk(g_z16, sa.w, lane, a0, a1);
        e += 4;
    }
    for (; e < degc; ++e) {
        acc_edge_pk(g_z16, g_pbuf[node * CAP + e], lane, a0, a1);
    }

    float2 f0 = __half22float2(a0);
    float2 f1 = __half22float2(a1);
    *(float4*)&part[warp][lane * 4] = make_float4(f0.x, f0.y, f1.x, f1.y);
    if (lane == 0) sgr[warp] = batch[node];
    __syncthreads();

    if (threadIdx.x < 128) {
        int d = threadIdx.x;
        float acc = part[0][d];
        int gc = sgr[0];
#pragma unroll
        for (int w = 1; w < 8; ++w) {
            int gw = sgr[w];
            if (gw != gc) {
                atomicAdd(&g_y[gc * D + d], acc);
                acc = 0.f; gc = gw;
            }
            acc += part[w][d];
        }
        atomicAdd(&g_y[gc * D + d], acc);
    }
}

// out[g] = (g_y[g]/cnt_g) @ W2 + b2 ; cnt via binary search on sorted batch;
// then restore zeroed-scratch invariant.
__global__ void out_clean_kernel(const int* __restrict__ batch,
                                 const float* __restrict__ W2,
                                 const float* __restrict__ b2,
                                 float* __restrict__ out) {
    int b = blockIdx.x;
    if (b < N_GRAPHS) {
        __shared__ float ys[D];
        int g = b, d = threadIdx.x;
        int lo = 0, hi = N_NODES;
        while (lo < hi) { int m = (lo + hi) >> 1; if (batch[m] < g) lo = m + 1; else hi = m; }
        int start = lo;
        lo = 0; hi = N_NODES;
        while (lo < hi) { int m = (lo + hi) >> 1; if (batch[m] < g + 1) lo = m + 1; else hi = m; }
        float cnt = fmaxf((float)(lo - start), 1.f);

        ys[d] = g_y[g * D + d] / cnt;
        g_y[g * D + d] = 0.f;            // restore invariant
        __syncthreads();
        float acc = b2[d];
#pragma unroll 8
        for (int k = 0; k < D; ++k) acc += ys[k] * W2[k * D + d];
        out[g * D + d] = acc;
    } else {
        const int nthr = (CLEAN_BLOCKS - N_GRAPHS) * 128;
        int i = (b - N_GRAPHS) * 128 + threadIdx.x;
        for (int j = i; j < N_NODES; j += nthr) g_fill[j] = 0;
    }
}

// ---------------- launch -----------------------------------------------------

extern "C" void kernel_launch(void* const* d_in, const int* in_sizes, int n_in,
                              void* d_out, int out_size) {
    const float* x     = (const float*)d_in[0];
    const int*   ei    = (const int*)d_in[1];    // int32 (JAX x64 disabled)
    const int*   batch = (const int*)d_in[2];
    const float* W1    = (const float*)d_in[3];
    const float* b1    = (const float*)d_in[4];
    const float* W2    = (const float*)d_in[5];
    const float* b2    = (const float*)d_in[6];
    float*       out   = (float*)d_out;

    __half* h16; cudaGetSymbolAddress((void**)&h16, g_h16);

    static cudaStream_t s_side = nullptr;
    static cudaEvent_t  e_fork = nullptr, e_join1 = nullptr, e_join2 = nullptr;
    if (s_side == nullptr) {
        cudaStreamCreateWithFlags(&s_side, cudaStreamNonBlocking);
        cudaEventCreateWithFlags(&e_fork, cudaEventDisableTiming);
        cudaEventCreateWithFlags(&e_join1, cudaEventDisableTiming);
        cudaEventCreateWithFlags(&e_join2, cudaEventDisableTiming);
    }

    // fork: main = GEMM1 ; side = fill -> dinv [join1] -> pack [join2]
    cudaEventRecord(e_fork, 0);
    cudaStreamWaitEvent(s_side, e_fork, 0);

    gemm_mma_kernel<<<GEMM_BLOCKS, 256>>>(x, W1, h16);

    fill_kernel<<<FILL_BLOCKS, 256, 0, s_side>>>(ei);
    dinv_kernel<<<DINV_BLOCKS, 256, 0, s_side>>>();
    cudaEventRecord(e_join1, s_side);
    pack_kernel<<<PACK_BLOCKS, 256, 0, s_side>>>();   // overlaps gather1
    cudaEventRecord(e_join2, s_side);

    // main: gather1 needs fill+dinv only (reads raw g_sbuf; pack writes g_pbuf)
    cudaStreamWaitEvent(0, e_join1, 0);
    gather1_kernel<<<GATHER_BLOCKS, 256>>>(b1);

    // gather2 consumes packed g_pbuf
    cudaStreamWaitEvent(0, e_join2, 0);
    gather2_kernel<<<GATHER_BLOCKS, 256>>>(batch);
    out_clean_kernel<<<CLEAN_BLOCKS, D>>>(batch, W2, b2, out);
}